// round 16
// baseline (speedup 1.0000x reference)
#include <cuda_runtime.h>
#include <math.h>

#define MAXN 100000
#define MAXE 1600000
#define F 32
#define SCAN_B 1024
#define NBLK ((MAXN + SCAN_B - 1) / SCAN_B)   // 98

__device__ int      g_cnt [MAXN];       // in-degree; zeroed at load, re-zeroed by k_xw1 each run
__device__ int      g_row [MAXN + 1];   // CSR row offsets
__device__ int      g_cur [MAXN];       // fill cursors
__device__ int      g_csr [MAXE];       // CSR src indices
__device__ int      g_bsum[NBLK];       // scan1 block sums (unscanned)
__device__ float    g_dinv[MAXN];
__device__ float    g_hA  [MAXN * F];   // gather source, pre-scaled by dinv[src]
__device__ float    g_hB  [MAXN * F];   // layer-1 aggregate (layer-2 aggregate never materialized)
__device__ unsigned g_max [F];          // zeroed at load, re-zeroed by head each run
__device__ unsigned g_done;             // ticket, re-zeroed by head each run

// ---------------------------------------------------------------- in-degree count (4 edges/thread)
__global__ void k_count(const int* __restrict__ ei, int E) {
    int e = (blockIdx.x * blockDim.x + threadIdx.x) * 4;
    if (e >= E) return;
    int4 d4 = *(const int4*)&ei[E + e];
    atomicAdd(&g_cnt[d4.x], 1);
    atomicAdd(&g_cnt[d4.y], 1);
    atomicAdd(&g_cnt[d4.z], 1);
    atomicAdd(&g_cnt[d4.w], 1);
}

// ---------------------------------------------------------------- scan pass 1: per-block exclusive scan
__global__ void k_scan1(int n) {
    __shared__ int sm[SCAN_B];
    int tid = threadIdx.x;
    int i = blockIdx.x * SCAN_B + tid;
    int v = (i < n) ? g_cnt[i] : 0;
    sm[tid] = v;
    __syncthreads();
#pragma unroll
    for (int off = 1; off < SCAN_B; off <<= 1) {
        int t = (tid >= off) ? sm[tid - off] : 0;
        __syncthreads();
        sm[tid] += t;
        __syncthreads();
    }
    if (i < n) g_row[i] = sm[tid] - v;            // block-local exclusive
    if (tid == SCAN_B - 1) g_bsum[blockIdx.x] = sm[tid];
}

// ------ fused: redundant bsum scan + row/cursor/dinv fixup + cnt reset + layer1 dense (TB=128)
__global__ void k_xw1(const float* __restrict__ x, const float* __restrict__ W1,
                      int n, int E, int nb) {
    __shared__ float Ws[8 * F];
    __shared__ int   excl[128];
    int t = threadIdx.x;
    for (int i = t; i < 8 * F; i += blockDim.x) Ws[i] = W1[i];
    int bv = (t < nb) ? g_bsum[t] : 0;
    excl[t] = bv;
    __syncthreads();
#pragma unroll
    for (int off = 1; off < 128; off <<= 1) {
        int tv = (t >= off) ? excl[t - off] : 0;
        __syncthreads();
        excl[t] += tv;
        __syncthreads();
    }
    int incl = excl[t];
    __syncthreads();
    excl[t] = incl - bv;                           // exclusive
    __syncthreads();

    int node = blockIdx.x * blockDim.x + t;
    if (node == 0) g_row[n] = E;
    if (node >= n) return;
    int r = g_row[node] + excl[node / SCAN_B];
    g_row[node] = r;
    g_cur[node] = r;
    int cnt = g_cnt[node];
    g_cnt[node] = 0;                               // restore invariant for next replay
    float d = rsqrtf((float)(cnt + 1));
    g_dinv[node] = d;
    float4 x0 = *(const float4*)&x[node * 8];
    float4 x1 = *(const float4*)&x[node * 8 + 4];
    float xv[8] = {x0.x, x0.y, x0.z, x0.w, x1.x, x1.y, x1.z, x1.w};
    float acc[F];
#pragma unroll
    for (int j = 0; j < F; j++) acc[j] = 0.f;
#pragma unroll
    for (int k = 0; k < 8; k++)
#pragma unroll
        for (int j = 0; j < F; j++)
            acc[j] = fmaf(xv[k], Ws[k * F + j], acc[j]);
    float4* pa = (float4*)&g_hA[node * F];
#pragma unroll
    for (int q = 0; q < 8; q++)
        pa[q] = make_float4(acc[q*4]*d, acc[q*4+1]*d, acc[q*4+2]*d, acc[q*4+3]*d);
}

// -------------------- CSR fill: 8 edges/thread, phase-split for atomic MLP
__global__ void k_fill(const int* __restrict__ ei, int E) {
    int e = (blockIdx.x * blockDim.x + threadIdx.x) * 8;
    if (e >= E) return;
    int4 s0 = *(const int4*)&ei[e];
    int4 s1 = *(const int4*)&ei[e + 4];
    int4 d0 = *(const int4*)&ei[E + e];
    int4 d1 = *(const int4*)&ei[E + e + 4];
    // phase 1: 8 independent cursor atomics in flight
    int p0 = atomicAdd(&g_cur[d0.x], 1);
    int p1 = atomicAdd(&g_cur[d0.y], 1);
    int p2 = atomicAdd(&g_cur[d0.z], 1);
    int p3 = atomicAdd(&g_cur[d0.w], 1);
    int p4 = atomicAdd(&g_cur[d1.x], 1);
    int p5 = atomicAdd(&g_cur[d1.y], 1);
    int p6 = atomicAdd(&g_cur[d1.z], 1);
    int p7 = atomicAdd(&g_cur[d1.w], 1);
    // phase 2: stores
    g_csr[p0] = s0.x;
    g_csr[p1] = s0.y;
    g_csr[p2] = s0.z;
    g_csr[p3] = s0.w;
    g_csr[p4] = s1.x;
    g_csr[p5] = s1.y;
    g_csr[p6] = s1.z;
    g_csr[p7] = s1.w;
}

// ---------------- layer-1 aggregate (warp-per-node): hB[v] = hA[v] + sum_{s in N(v)} hA[s]
__global__ void k_agg(int n) {
    int lane = threadIdx.x & 31, w = threadIdx.x >> 5;
    int node = blockIdx.x * 8 + w;
    if (node >= n) return;
    int g  = lane >> 3;          // edge group 0..3
    int sl = lane & 7;           // float4 slot 0..7
    int start = g_row[node], end = g_row[node + 1];
    float4 acc = make_float4(0.f, 0.f, 0.f, 0.f);
    for (int base = start + g; base < end; base += 4) {
        int s = g_csr[base];
        float4 v = *(const float4*)&g_hA[s * F + sl * 4];
        acc.x += v.x; acc.y += v.y; acc.z += v.z; acc.w += v.w;
    }
#pragma unroll
    for (int off = 16; off >= 8; off >>= 1) {
        acc.x += __shfl_xor_sync(0xffffffffu, acc.x, off);
        acc.y += __shfl_xor_sync(0xffffffffu, acc.y, off);
        acc.z += __shfl_xor_sync(0xffffffffu, acc.z, off);
        acc.w += __shfl_xor_sync(0xffffffffu, acc.w, off);
    }
    if (lane < 8) {
        float4 sv = *(const float4*)&g_hA[node * F + lane * 4];
        *(float4*)&g_hB[node * F + lane * 4] =
            make_float4(acc.x + sv.x, acc.y + sv.y, acc.z + sv.z, acc.w + sv.w);
    }
}

// -------- between layers (thread-per-node): r = relu(dinv*hB + b1); hA = (r@W2)*dinv
__global__ void k_mid(const float* __restrict__ b1, const float* __restrict__ W2, int n) {
    __shared__ float Ws[F * F];
    __shared__ float bs[F];
    int t = threadIdx.x;
    for (int i = t; i < F * F; i += blockDim.x) Ws[i] = W2[i];
    if (t < F) bs[t] = b1[t];
    __syncthreads();
    int node = blockIdx.x * blockDim.x + t;
    if (node >= n) return;
    float d = g_dinv[node];
    const float4* hb = (const float4*)&g_hB[node * F];
    float acc[F];
#pragma unroll
    for (int j = 0; j < F; j++) acc[j] = 0.f;
#pragma unroll
    for (int q = 0; q < 8; q++) {
        float4 hv = hb[q];
        float r0 = fmaxf(fmaf(d, hv.x, bs[q*4+0]), 0.f);
        float r1 = fmaxf(fmaf(d, hv.y, bs[q*4+1]), 0.f);
        float r2 = fmaxf(fmaf(d, hv.z, bs[q*4+2]), 0.f);
        float r3 = fmaxf(fmaf(d, hv.w, bs[q*4+3]), 0.f);
#pragma unroll
        for (int j = 0; j < F; j++) {
            acc[j] = fmaf(r0, Ws[(q*4+0) * F + j], acc[j]);
            acc[j] = fmaf(r1, Ws[(q*4+1) * F + j], acc[j]);
            acc[j] = fmaf(r2, Ws[(q*4+2) * F + j], acc[j]);
            acc[j] = fmaf(r3, Ws[(q*4+3) * F + j], acc[j]);
        }
    }
    float4* pa = (float4*)&g_hA[node * F];
#pragma unroll
    for (int q = 0; q < 8; q++)
        pa[q] = make_float4(acc[q*4]*d, acc[q*4+1]*d, acc[q*4+2]*d, acc[q*4+3]*d);
}

// ------ fused layer-2 aggregate + relu/bias + global max pool + FC head (grid-stride, no hB)
__global__ void k_agg_pool(const float* __restrict__ b2, const float* __restrict__ fcW,
                           const float* __restrict__ fcb, float* __restrict__ out, int n) {
    __shared__ float smax[8][F];
    __shared__ bool  last;
    int lane = threadIdx.x & 31, w = threadIdx.x >> 5;
    int g  = lane >> 3;
    int sl = lane & 7;
    float4 bias = (lane < 8) ? ((const float4*)b2)[sl] : make_float4(0.f, 0.f, 0.f, 0.f);
    float4 rmax = make_float4(0.f, 0.f, 0.f, 0.f);    // relu outputs >= 0

    for (int node = blockIdx.x * 8 + w; node < n; node += gridDim.x * 8) {
        int start = g_row[node], end = g_row[node + 1];
        float4 acc = make_float4(0.f, 0.f, 0.f, 0.f);
        for (int base = start + g; base < end; base += 4) {
            int s = g_csr[base];
            float4 v = *(const float4*)&g_hA[s * F + sl * 4];
            acc.x += v.x; acc.y += v.y; acc.z += v.z; acc.w += v.w;
        }
#pragma unroll
        for (int off = 16; off >= 8; off >>= 1) {
            acc.x += __shfl_xor_sync(0xffffffffu, acc.x, off);
            acc.y += __shfl_xor_sync(0xffffffffu, acc.y, off);
            acc.z += __shfl_xor_sync(0xffffffffu, acc.z, off);
            acc.w += __shfl_xor_sync(0xffffffffu, acc.w, off);
        }
        if (lane < 8) {
            float4 sv = *(const float4*)&g_hA[node * F + lane * 4];
            float d = g_dinv[node];
            rmax.x = fmaxf(rmax.x, fmaf(d, acc.x + sv.x, bias.x));
            rmax.y = fmaxf(rmax.y, fmaf(d, acc.y + sv.y, bias.y));
            rmax.z = fmaxf(rmax.z, fmaf(d, acc.z + sv.z, bias.z));
            rmax.w = fmaxf(rmax.w, fmaf(d, acc.w + sv.w, bias.w));
        }
    }
    if (lane < 8) *(float4*)&smax[w][sl * 4] = rmax;   // relu via max with 0-init
    __syncthreads();
    if (w == 0 && lane < 8) {
        float4 mm = *(const float4*)&smax[0][sl * 4];
#pragma unroll
        for (int i = 1; i < 8; i++) {
            float4 v = *(const float4*)&smax[i][sl * 4];
            mm.x = fmaxf(mm.x, v.x); mm.y = fmaxf(mm.y, v.y);
            mm.z = fmaxf(mm.z, v.z); mm.w = fmaxf(mm.w, v.w);
        }
        atomicMax(&g_max[sl * 4 + 0], __float_as_uint(fmaxf(mm.x, 0.f)));
        atomicMax(&g_max[sl * 4 + 1], __float_as_uint(fmaxf(mm.y, 0.f)));
        atomicMax(&g_max[sl * 4 + 2], __float_as_uint(fmaxf(mm.z, 0.f)));
        atomicMax(&g_max[sl * 4 + 3], __float_as_uint(fmaxf(mm.w, 0.f)));
        __threadfence();
    }
    __syncthreads();
    if (threadIdx.x == 0)
        last = (atomicAdd(&g_done, 1u) == gridDim.x - 1);
    __syncthreads();
    if (!last) return;
    if (w == 0) {
        float gv = __uint_as_float(*(volatile unsigned*)&g_max[lane]);
        smax[0][lane] = gv;
        __syncwarp();
        float logit = 0.f;
        if (lane < 5) {
            logit = fcb[lane];
#pragma unroll
            for (int k = 0; k < F; k++) logit = fmaf(smax[0][k], fcW[k * 5 + lane], logit);
        }
        float lv = (lane < 5) ? logit : -1e30f;
        float mx = lv;
#pragma unroll
        for (int off = 1; off < 32; off <<= 1) mx = fmaxf(mx, __shfl_xor_sync(0xffffffffu, mx, off));
        float ex = (lane < 5) ? __expf(logit - mx) : 0.f;
        float s = ex;
#pragma unroll
        for (int off = 1; off < 32; off <<= 1) s += __shfl_xor_sync(0xffffffffu, s, off);
        float lse = logf(s);
        if (lane < 5) out[lane] = logit - mx - lse;
        g_max[lane] = 0u;                  // restore invariants for next replay
        if (lane == 0) g_done = 0u;
    }
}

// ================================================================ launch
extern "C" void kernel_launch(void* const* d_in, const int* in_sizes, int n_in,
                              void* d_out, int out_size) {
    const float* x   = (const float*)d_in[0];
    const int*   ei  = (const int*)d_in[1];
    const float* W1  = (const float*)d_in[2];
    const float* b1  = (const float*)d_in[3];
    const float* W2  = (const float*)d_in[4];
    const float* b2  = (const float*)d_in[5];
    const float* fcW = (const float*)d_in[6];
    const float* fcb = (const float*)d_in[7];
    float*       out = (float*)d_out;

    int n = in_sizes[0] / 8;       // 100000
    int E = in_sizes[1] / 2;       // 1600000

    const int TB = 256;
    int gridE4  = (E / 4 + TB - 1) / TB;
    int gridE8  = (E / 8 + TB - 1) / TB;
    int gridNW  = (n + 7) / 8;                 // warp-per-node
    int nScanB  = (n + SCAN_B - 1) / SCAN_B;   // 98
    int gridD   = (n + 127) / 128;

    k_count   <<<gridE4, TB>>>(ei, E);
    k_scan1   <<<nScanB, SCAN_B>>>(n);
    k_xw1     <<<gridD, 128>>>(x, W1, n, E, nScanB);
    k_fill    <<<gridE8, TB>>>(ei, E);
    k_agg     <<<gridNW, TB>>>(n);
    k_mid     <<<gridD, 128>>>(b1, W2, n);
    k_agg_pool<<<1024, TB>>>(b2, fcW, fcb, out, n);
}

// round 17
// speedup vs baseline: 1.0942x; 1.0942x over previous
#include <cuda_runtime.h>
#include <math.h>

#define MAXN 100000
#define MAXE 1600000
#define F 32
#define SCAN_B 1024
#define NBLK ((MAXN + SCAN_B - 1) / SCAN_B)   // 98

__device__ int      g_cnt [MAXN];       // in-degree; zeroed at load, re-zeroed by k_xw1 each run
__device__ int      g_row [MAXN + 1];   // CSR row offsets
__device__ int      g_cur [MAXN];       // fill cursors
__device__ int      g_csr [MAXE];       // CSR src indices
__device__ int      g_bsum[NBLK];       // scan1 block sums (unscanned)
__device__ float    g_dinv[MAXN];
__device__ float    g_hA  [MAXN * F];   // gather source, pre-scaled by dinv[src]
__device__ float    g_hB  [MAXN * F];   // layer-1 aggregate
__device__ unsigned g_max [F];          // zeroed at load, re-zeroed by head each run
__device__ unsigned g_done;             // ticket, re-zeroed by head each run

// ---------------------------------------------------------------- in-degree count (4 edges/thread)
__global__ void k_count(const int* __restrict__ ei, int E) {
    int e = (blockIdx.x * blockDim.x + threadIdx.x) * 4;
    if (e >= E) return;
    int4 d4 = *(const int4*)&ei[E + e];
    atomicAdd(&g_cnt[d4.x], 1);
    atomicAdd(&g_cnt[d4.y], 1);
    atomicAdd(&g_cnt[d4.z], 1);
    atomicAdd(&g_cnt[d4.w], 1);
}

// ----------------- scan pass 1: per-block exclusive scan, shfl-based (3 barriers instead of 20)
__global__ void k_scan1(int n) {
    __shared__ int wsum[32];              // per-warp totals
    int tid  = threadIdx.x;
    int lane = tid & 31, w = tid >> 5;    // 32 warps
    int i = blockIdx.x * SCAN_B + tid;
    int v = (i < n) ? g_cnt[i] : 0;
    // warp inclusive scan
    int sc = v;
#pragma unroll
    for (int off = 1; off < 32; off <<= 1) {
        int t = __shfl_up_sync(0xffffffffu, sc, off);
        if (lane >= off) sc += t;
    }
    if (lane == 31) wsum[w] = sc;
    __syncthreads();
    // warp 0 scans the 32 warp totals
    if (w == 0) {
        int ws = wsum[lane];
#pragma unroll
        for (int off = 1; off < 32; off <<= 1) {
            int t = __shfl_up_sync(0xffffffffu, ws, off);
            if (lane >= off) ws += t;
        }
        wsum[lane] = ws;                  // inclusive over warps
    }
    __syncthreads();
    int base = (w > 0) ? wsum[w - 1] : 0;
    int incl = base + sc;
    if (i < n) g_row[i] = incl - v;       // block-local exclusive
    if (tid == SCAN_B - 1) g_bsum[blockIdx.x] = incl;
}

// ------ fused: redundant bsum scan + row/cursor/dinv fixup + cnt reset + layer1 dense (TB=128)
__global__ void k_xw1(const float* __restrict__ x, const float* __restrict__ W1,
                      int n, int E, int nb) {
    __shared__ float Ws[8 * F];
    __shared__ int   excl[128];
    int t = threadIdx.x;
    for (int i = t; i < 8 * F; i += blockDim.x) Ws[i] = W1[i];
    int bv = (t < nb) ? g_bsum[t] : 0;
    excl[t] = bv;
    __syncthreads();
#pragma unroll
    for (int off = 1; off < 128; off <<= 1) {
        int tv = (t >= off) ? excl[t - off] : 0;
        __syncthreads();
        excl[t] += tv;
        __syncthreads();
    }
    int incl = excl[t];
    __syncthreads();
    excl[t] = incl - bv;                           // exclusive
    __syncthreads();

    int node = blockIdx.x * blockDim.x + t;
    if (node == 0) g_row[n] = E;
    if (node >= n) return;
    int r = g_row[node] + excl[node / SCAN_B];
    g_row[node] = r;
    g_cur[node] = r;
    int cnt = g_cnt[node];
    g_cnt[node] = 0;                               // restore invariant for next replay
    float d = rsqrtf((float)(cnt + 1));
    g_dinv[node] = d;
    float4 x0 = *(const float4*)&x[node * 8];
    float4 x1 = *(const float4*)&x[node * 8 + 4];
    float xv[8] = {x0.x, x0.y, x0.z, x0.w, x1.x, x1.y, x1.z, x1.w};
    float acc[F];
#pragma unroll
    for (int j = 0; j < F; j++) acc[j] = 0.f;
#pragma unroll
    for (int k = 0; k < 8; k++)
#pragma unroll
        for (int j = 0; j < F; j++)
            acc[j] = fmaf(xv[k], Ws[k * F + j], acc[j]);
    float4* pa = (float4*)&g_hA[node * F];
#pragma unroll
    for (int q = 0; q < 8; q++)
        pa[q] = make_float4(acc[q*4]*d, acc[q*4+1]*d, acc[q*4+2]*d, acc[q*4+3]*d);
}

// ---------------------------------------------------------------- CSR fill (4 edges/thread, R14 form)
__global__ void k_fill(const int* __restrict__ ei, int E) {
    int e = (blockIdx.x * blockDim.x + threadIdx.x) * 4;
    if (e >= E) return;
    int4 s4 = *(const int4*)&ei[e];
    int4 d4 = *(const int4*)&ei[E + e];
    g_csr[atomicAdd(&g_cur[d4.x], 1)] = s4.x;
    g_csr[atomicAdd(&g_cur[d4.y], 1)] = s4.y;
    g_csr[atomicAdd(&g_cur[d4.z], 1)] = s4.z;
    g_csr[atomicAdd(&g_cur[d4.w], 1)] = s4.w;
}

// ---------------- layer-1 aggregate (warp-per-node): hB[v] = hA[v] + sum_{s in N(v)} hA[s]
__global__ void k_agg(int n) {
    int lane = threadIdx.x & 31, w = threadIdx.x >> 5;
    int node = blockIdx.x * 8 + w;
    if (node >= n) return;
    int g  = lane >> 3;          // edge group 0..3
    int sl = lane & 7;           // float4 slot 0..7
    int start = g_row[node], end = g_row[node + 1];
    float4 acc = make_float4(0.f, 0.f, 0.f, 0.f);
    for (int base = start + g; base < end; base += 4) {
        int s = g_csr[base];
        float4 v = *(const float4*)&g_hA[s * F + sl * 4];
        acc.x += v.x; acc.y += v.y; acc.z += v.z; acc.w += v.w;
    }
#pragma unroll
    for (int off = 16; off >= 8; off >>= 1) {
        acc.x += __shfl_xor_sync(0xffffffffu, acc.x, off);
        acc.y += __shfl_xor_sync(0xffffffffu, acc.y, off);
        acc.z += __shfl_xor_sync(0xffffffffu, acc.z, off);
        acc.w += __shfl_xor_sync(0xffffffffu, acc.w, off);
    }
    if (lane < 8) {
        float4 sv = *(const float4*)&g_hA[node * F + lane * 4];
        *(float4*)&g_hB[node * F + lane * 4] =
            make_float4(acc.x + sv.x, acc.y + sv.y, acc.z + sv.z, acc.w + sv.w);
    }
}

// -------- between layers (thread-per-node): r = relu(dinv*hB + b1); hA = (r@W2)*dinv
__global__ void k_mid(const float* __restrict__ b1, const float* __restrict__ W2, int n) {
    __shared__ float Ws[F * F];
    __shared__ float bs[F];
    int t = threadIdx.x;
    for (int i = t; i < F * F; i += blockDim.x) Ws[i] = W2[i];
    if (t < F) bs[t] = b1[t];
    __syncthreads();
    int node = blockIdx.x * blockDim.x + t;
    if (node >= n) return;
    float d = g_dinv[node];
    const float4* hb = (const float4*)&g_hB[node * F];
    float acc[F];
#pragma unroll
    for (int j = 0; j < F; j++) acc[j] = 0.f;
#pragma unroll
    for (int q = 0; q < 8; q++) {
        float4 hv = hb[q];
        float r0 = fmaxf(fmaf(d, hv.x, bs[q*4+0]), 0.f);
        float r1 = fmaxf(fmaf(d, hv.y, bs[q*4+1]), 0.f);
        float r2 = fmaxf(fmaf(d, hv.z, bs[q*4+2]), 0.f);
        float r3 = fmaxf(fmaf(d, hv.w, bs[q*4+3]), 0.f);
#pragma unroll
        for (int j = 0; j < F; j++) {
            acc[j] = fmaf(r0, Ws[(q*4+0) * F + j], acc[j]);
            acc[j] = fmaf(r1, Ws[(q*4+1) * F + j], acc[j]);
            acc[j] = fmaf(r2, Ws[(q*4+2) * F + j], acc[j]);
            acc[j] = fmaf(r3, Ws[(q*4+3) * F + j], acc[j]);
        }
    }
    float4* pa = (float4*)&g_hA[node * F];
#pragma unroll
    for (int q = 0; q < 8; q++)
        pa[q] = make_float4(acc[q*4]*d, acc[q*4+1]*d, acc[q*4+2]*d, acc[q*4+3]*d);
}

// ---------------- fused maxpool + FC head + log_softmax (R14 form)
__global__ void k_pool_head(const float* __restrict__ b2, const float* __restrict__ fcW,
                            const float* __restrict__ fcb, float* __restrict__ out, int n) {
    __shared__ float sm[8][F];
    __shared__ bool  last;
    int lane = threadIdx.x & 31, w = threadIdx.x >> 5;
    float bias = b2[lane];
    float m = 0.f;
    for (int node = blockIdx.x * 8 + w; node < n; node += gridDim.x * 8) {
        float d = g_dinv[node];
        m = fmaxf(m, fmaxf(fmaf(d, g_hB[node * F + lane], bias), 0.f));
    }
    sm[w][lane] = m;
    __syncthreads();
    if (w == 0) {
        float mm = sm[0][lane];
#pragma unroll
        for (int i = 1; i < 8; i++) mm = fmaxf(mm, sm[i][lane]);
        atomicMax(&g_max[lane], __float_as_uint(mm));
        __threadfence();
    }
    __syncthreads();
    if (threadIdx.x == 0)
        last = (atomicAdd(&g_done, 1u) == gridDim.x - 1);
    __syncthreads();
    if (!last) return;
    if (w == 0) {
        float gv = __uint_as_float(*(volatile unsigned*)&g_max[lane]);
        sm[0][lane] = gv;
        __syncwarp();
        float logit = 0.f;
        if (lane < 5) {
            logit = fcb[lane];
#pragma unroll
            for (int k = 0; k < F; k++) logit = fmaf(sm[0][k], fcW[k * 5 + lane], logit);
        }
        float lv = (lane < 5) ? logit : -1e30f;
        float mx = lv;
#pragma unroll
        for (int off = 1; off < 32; off <<= 1) mx = fmaxf(mx, __shfl_xor_sync(0xffffffffu, mx, off));
        float ex = (lane < 5) ? __expf(logit - mx) : 0.f;
        float s = ex;
#pragma unroll
        for (int off = 1; off < 32; off <<= 1) s += __shfl_xor_sync(0xffffffffu, s, off);
        float lse = logf(s);
        if (lane < 5) out[lane] = logit - mx - lse;
        g_max[lane] = 0u;
        if (lane == 0) g_done = 0u;
    }
}

// ================================================================ launch
extern "C" void kernel_launch(void* const* d_in, const int* in_sizes, int n_in,
                              void* d_out, int out_size) {
    const float* x   = (const float*)d_in[0];
    const int*   ei  = (const int*)d_in[1];
    const float* W1  = (const float*)d_in[2];
    const float* b1  = (const float*)d_in[3];
    const float* W2  = (const float*)d_in[4];
    const float* b2  = (const float*)d_in[5];
    const float* fcW = (const float*)d_in[6];
    const float* fcb = (const float*)d_in[7];
    float*       out = (float*)d_out;

    int n = in_sizes[0] / 8;       // 100000
    int E = in_sizes[1] / 2;       // 1600000

    const int TB = 256;
    int gridE4  = (E / 4 + TB - 1) / TB;
    int gridNW  = (n + 7) / 8;                 // warp-per-node
    int nScanB  = (n + SCAN_B - 1) / SCAN_B;   // 98
    int gridD   = (n + 127) / 128;

    k_count    <<<gridE4, TB>>>(ei, E);
    k_scan1    <<<nScanB, SCAN_B>>>(n);
    k_xw1      <<<gridD, 128>>>(x, W1, n, E, nScanB);
    k_fill     <<<gridE4, TB>>>(ei, E);
    k_agg      <<<gridNW, TB>>>(n);
    k_mid      <<<gridD, 128>>>(b1, W2, n);
    k_agg      <<<gridNW, TB>>>(n);
    k_pool_head<<<512, TB>>>(b2, fcW, fcb, out, n);
}